// round 1
// baseline (speedup 1.0000x reference)
#include <cuda_runtime.h>
#include <cuda_bf16.h>
#include <math.h>

#define SEQ   2048
#define HDIM  512
#define NH    6
#define VOCAB 32000
#define G3    1536          // 3*HDIM
#define GRU_NCTA 64

// ---------------- scratch (device globals; no allocations allowed) -------------
__device__ float g_x   [SEQ*HDIM];                 // embeddings
__device__ float g_q   [NH*SEQ*HDIM];
__device__ float g_k   [NH*SEQ*HDIM];
__device__ float g_v   [NH*SEQ*HDIM];
__device__ float g_sc  [(size_t)NH*SEQ*SEQ];       // attention scores / probs
__device__ float g_cat [SEQ*NH*HDIM];              // concatenated heads (s, h*512+e)
__device__ float g_mha [SEQ*HDIM];
__device__ float g_xln [SEQ*HDIM];                 // post-LN sequence (GRU input)
__device__ float g_gi  [SEQ*G3];                   // x @ W_ih^T + b_ih, all timesteps
__device__ float g_h   [2*HDIM];                   // GRU hidden double buffer
__device__ float g_logits[VOCAB];
__device__ float g_lse;
__device__ unsigned g_count;
__device__ unsigned g_release;

__device__ __forceinline__ float sigmoidf_(float x){ return 1.0f/(1.0f+expf(-x)); }

// ---------------- embedding gather ---------------------------------------------
__global__ void embed_kernel(const int* __restrict__ tok,
                             const float* __restrict__ emb)
{
    int s = blockIdx.x;
    long long t = tok[s];
    const float4* src = (const float4*)(emb + t*HDIM);
    float4* dst = (float4*)(g_x + (long long)s*HDIM);
    int i = threadIdx.x;               // 128 threads, 128 float4 = 512 floats
    dst[i] = src[i];
}

// ---------------- fp32 tiled GEMM: C = alpha*(A@B[^T]) + bias[col] -------------
// BM=BN=128, BK=16, 256 threads, 8x8 microtile per thread.
template<bool TRANS_B>
__global__ void gemm128(const float* __restrict__ A, const float* __restrict__ B,
                        const float* __restrict__ bias, float* __restrict__ C,
                        int M, int N, int K, int lda, int ldb, int ldc,
                        long long sA, long long sB, long long sC, long long sBias,
                        float alpha)
{
    __shared__ float As[16][132];
    __shared__ float Bs[16][132];
    A += (long long)blockIdx.z * sA;
    B += (long long)blockIdx.z * sB;
    C += (long long)blockIdx.z * sC;
    const float* bi = bias ? (bias + (long long)blockIdx.z * sBias) : (const float*)0;

    const int bm = blockIdx.y * 128;
    const int bn = blockIdx.x * 128;
    const int tid = threadIdx.x;
    const int tx = tid & 15, ty = tid >> 4;

    float acc[8][8];
    #pragma unroll
    for (int i = 0; i < 8; i++)
        #pragma unroll
        for (int j = 0; j < 8; j++) acc[i][j] = 0.0f;

    for (int k0 = 0; k0 < K; k0 += 16) {
        #pragma unroll
        for (int i = 0; i < 8; i++) {
            int idx = tid + i*256;
            int m = idx >> 4, k = idx & 15;
            As[k][m] = A[(long long)(bm+m)*lda + (k0+k)];
        }
        #pragma unroll
        for (int i = 0; i < 8; i++) {
            int idx = tid + i*256;
            if (TRANS_B) {
                int n = idx >> 4, k = idx & 15;
                Bs[k][n] = B[(long long)(bn+n)*ldb + (k0+k)];
            } else {
                int k = idx >> 7, n = idx & 127;
                Bs[k][n] = B[(long long)(k0+k)*ldb + (bn+n)];
            }
        }
        __syncthreads();
        #pragma unroll
        for (int kk = 0; kk < 16; kk++) {
            float4 a0 = *(const float4*)&As[kk][ty*8];
            float4 a1 = *(const float4*)&As[kk][ty*8+4];
            float4 b0 = *(const float4*)&Bs[kk][tx*8];
            float4 b1 = *(const float4*)&Bs[kk][tx*8+4];
            float af[8] = {a0.x,a0.y,a0.z,a0.w,a1.x,a1.y,a1.z,a1.w};
            float bf[8] = {b0.x,b0.y,b0.z,b0.w,b1.x,b1.y,b1.z,b1.w};
            #pragma unroll
            for (int i = 0; i < 8; i++)
                #pragma unroll
                for (int j = 0; j < 8; j++)
                    acc[i][j] += af[i]*bf[j];
        }
        __syncthreads();
    }
    #pragma unroll
    for (int i = 0; i < 8; i++) {
        int row = bm + ty*8 + i;
        float* cp = C + (long long)row*ldc + bn + tx*8;
        #pragma unroll
        for (int j = 0; j < 8; j++) {
            float vv = alpha*acc[i][j];
            if (bi) vv += bi[bn + tx*8 + j];
            cp[j] = vv;
        }
    }
}

// ---------------- row softmax over length-2048 rows ----------------------------
__global__ void softmax2048(float* __restrict__ S)
{
    __shared__ float red[32];
    float* row = S + (long long)blockIdx.x * 2048;
    int tid = threadIdx.x;                         // 256
    float v[8];
    float m = -1e30f;
    #pragma unroll
    for (int i = 0; i < 8; i++) { v[i] = row[tid + i*256]; m = fmaxf(m, v[i]); }
    #pragma unroll
    for (int o = 16; o > 0; o >>= 1) m = fmaxf(m, __shfl_xor_sync(~0u, m, o));
    if ((tid & 31) == 0) red[tid >> 5] = m;
    __syncthreads();
    if (tid == 0) {
        float x = red[0];
        #pragma unroll
        for (int i = 1; i < 8; i++) x = fmaxf(x, red[i]);
        red[0] = x;
    }
    __syncthreads();
    m = red[0];
    __syncthreads();
    float s = 0.0f;
    #pragma unroll
    for (int i = 0; i < 8; i++) { v[i] = expf(v[i] - m); s += v[i]; }
    #pragma unroll
    for (int o = 16; o > 0; o >>= 1) s += __shfl_xor_sync(~0u, s, o);
    if ((tid & 31) == 0) red[tid >> 5] = s;
    __syncthreads();
    if (tid == 0) {
        float x = 0.0f;
        #pragma unroll
        for (int i = 0; i < 8; i++) x += red[i];
        red[0] = x;
    }
    __syncthreads();
    float inv = 1.0f / red[0];
    #pragma unroll
    for (int i = 0; i < 8; i++) row[tid + i*256] = v[i]*inv;
}

// ---------------- residual + LayerNorm -----------------------------------------
__global__ void resid_ln(const float* __restrict__ gamma, const float* __restrict__ beta)
{
    __shared__ float r1[8], r2[8];
    int s = blockIdx.x, tid = threadIdx.x;         // 256 threads
    const float* xr = g_x   + (long long)s*HDIM;
    const float* mr = g_mha + (long long)s*HDIM;
    float y0 = xr[tid]       + mr[tid];
    float y1 = xr[tid + 256] + mr[tid + 256];
    float sum = y0 + y1, sq = y0*y0 + y1*y1;
    #pragma unroll
    for (int o = 16; o > 0; o >>= 1) {
        sum += __shfl_xor_sync(~0u, sum, o);
        sq  += __shfl_xor_sync(~0u, sq,  o);
    }
    if ((tid & 31) == 0) { r1[tid >> 5] = sum; r2[tid >> 5] = sq; }
    __syncthreads();
    if (tid == 0) {
        float a = 0.0f, b = 0.0f;
        #pragma unroll
        for (int i = 0; i < 8; i++) { a += r1[i]; b += r2[i]; }
        r1[0] = a; r2[0] = b;
    }
    __syncthreads();
    float mu  = r1[0]*(1.0f/512.0f);
    float var = r2[0]*(1.0f/512.0f) - mu*mu;
    float rstd = rsqrtf(var + 1e-5f);
    g_xln[(long long)s*HDIM + tid]       = (y0 - mu)*rstd*gamma[tid]       + beta[tid];
    g_xln[(long long)s*HDIM + 256 + tid] = (y1 - mu)*rstd*gamma[tid + 256] + beta[tid + 256];
}

// ---------------- GRU init (also resets barrier state each launch) -------------
__global__ void gru_init(const float* __restrict__ dec_hid)
{
    int i = threadIdx.x;                           // 512
    g_h[i] = dec_hid[i];
    if (i == 0) { g_count = 0u; g_release = 0u; }
}

// ---------------- persistent sequential GRU ------------------------------------
// 64 CTAs x 256 threads. Warp w of CTA c owns h-element jj = c*8+w and its three
// gate rows (jj, jj+512, jj+1024). Lane l holds W_hh[row][l+32i], i=0..15 in regs.
__global__ void gru_kernel(const float* __restrict__ W_hh,
                           const float* __restrict__ b_hh)
{
    const int warp = threadIdx.x >> 5, lane = threadIdx.x & 31;
    const int jj = blockIdx.x * 8 + warp;          // 0..511

    float wr0[16], wr1[16], wr2[16];
    const float* w0 = W_hh + (long long)(jj        )*HDIM + lane;
    const float* w1 = W_hh + (long long)(jj +  512 )*HDIM + lane;
    const float* w2 = W_hh + (long long)(jj + 1024 )*HDIM + lane;
    #pragma unroll
    for (int i = 0; i < 16; i++) { wr0[i] = w0[32*i]; wr1[i] = w1[32*i]; wr2[i] = w2[32*i]; }
    const float bh0 = b_hh[jj], bh1 = b_hh[jj + 512], bh2 = b_hh[jj + 1024];

    for (int t = 0; t < SEQ; t++) {
        const float* hb = g_h + (t & 1)*HDIM;
        // prefetch gi for this step (same address across lanes -> broadcast)
        float gr = __ldcg(&g_gi[(long long)t*G3 + jj]);
        float gz = __ldcg(&g_gi[(long long)t*G3 + jj + 512]);
        float gn = __ldcg(&g_gi[(long long)t*G3 + jj + 1024]);
        float hprev = __ldcg(&hb[jj]);

        float hv[16];
        #pragma unroll
        for (int i = 0; i < 16; i++) hv[i] = __ldcg(&hb[lane + 32*i]);

        float a0 = 0.0f, a1 = 0.0f, a2 = 0.0f;
        #pragma unroll
        for (int i = 0; i < 16; i++) {
            a0 += hv[i]*wr0[i];
            a1 += hv[i]*wr1[i];
            a2 += hv[i]*wr2[i];
        }
        #pragma unroll
        for (int o = 16; o > 0; o >>= 1) {
            a0 += __shfl_xor_sync(~0u, a0, o);
            a1 += __shfl_xor_sync(~0u, a1, o);
            a2 += __shfl_xor_sync(~0u, a2, o);
        }

        if (lane == 0) {
            float r = sigmoidf_(gr + a0 + bh0);
            float z = sigmoidf_(gz + a1 + bh1);
            float n = tanhf(gn + r*(a2 + bh2));
            float hnew = (1.0f - z)*n + z*hprev;
            g_h[((t + 1) & 1)*HDIM + jj] = hnew;
            __threadfence();                       // make hnew visible before arrive
        }
        __syncthreads();
        if (threadIdx.x == 0) {
            unsigned arrived = atomicAdd(&g_count, 1u) + 1u;
            if (arrived == (unsigned)GRU_NCTA*(unsigned)(t + 1)) {
                atomicExch(&g_release, (unsigned)(t + 1));
            } else {
                while (*(volatile unsigned*)&g_release < (unsigned)(t + 1)) { }
            }
        }
        __syncthreads();
        __threadfence();                           // acquire before reading new h
    }
}

// ---------------- final projection: logits = h @ W_out + b_out -----------------
__global__ void logits_kernel(const float* __restrict__ W_out,
                              const float* __restrict__ b_out)
{
    __shared__ float hs[HDIM];
    for (int i = threadIdx.x; i < HDIM; i += 256) hs[i] = g_h[i];  // final h in buf 0
    __syncthreads();
    int v = blockIdx.x*256 + threadIdx.x;
    if (v >= VOCAB) return;
    float acc = b_out[v];
    #pragma unroll 4
    for (int d = 0; d < HDIM; d++) acc += hs[d]*W_out[(long long)d*VOCAB + v];
    g_logits[v] = acc;
}

__global__ void lse_kernel()
{
    __shared__ float red[32];
    int tid = threadIdx.x;                         // 1024
    float m = -1e30f;
    for (int i = tid; i < VOCAB; i += 1024) m = fmaxf(m, g_logits[i]);
    #pragma unroll
    for (int o = 16; o > 0; o >>= 1) m = fmaxf(m, __shfl_xor_sync(~0u, m, o));
    if ((tid & 31) == 0) red[tid >> 5] = m;
    __syncthreads();
    if (tid == 0) {
        float x = red[0];
        #pragma unroll
        for (int i = 1; i < 32; i++) x = fmaxf(x, red[i]);
        red[0] = x;
    }
    __syncthreads();
    m = red[0];
    __syncthreads();
    float s = 0.0f;
    for (int i = tid; i < VOCAB; i += 1024) s += expf(g_logits[i] - m);
    #pragma unroll
    for (int o = 16; o > 0; o >>= 1) s += __shfl_xor_sync(~0u, s, o);
    if ((tid & 31) == 0) red[tid >> 5] = s;
    __syncthreads();
    if (tid == 0) {
        float x = 0.0f;
        #pragma unroll
        for (int i = 0; i < 32; i++) x += red[i];
        g_lse = m + logf(x);
    }
}

__global__ void out_kernel(float* __restrict__ out)
{
    int i = blockIdx.x*256 + threadIdx.x;
    if (i < VOCAB)            out[i] = g_logits[i] - g_lse;
    else if (i < VOCAB+HDIM)  out[i] = g_h[i - VOCAB];      // dec_hid_new (h in buf 0)
}

// ================================ host side =====================================
extern "C" void kernel_launch(void* const* d_in, const int* in_sizes, int n_in,
                              void* d_out, int out_size)
{
    const int*   tok     = (const int*)  d_in[0];
    const float* dec_hid = (const float*)d_in[1];
    const float* emb     = (const float*)d_in[2];
    const float* Wq      = (const float*)d_in[3];
    const float* bq      = (const float*)d_in[4];
    const float* Wk      = (const float*)d_in[5];
    const float* bk      = (const float*)d_in[6];
    const float* Wv      = (const float*)d_in[7];
    const float* bv      = (const float*)d_in[8];
    const float* Wo      = (const float*)d_in[9];
    const float* bo      = (const float*)d_in[10];
    const float* gamma   = (const float*)d_in[11];
    const float* beta    = (const float*)d_in[12];
    const float* W_ih    = (const float*)d_in[13];
    const float* W_hh    = (const float*)d_in[14];
    const float* b_ih    = (const float*)d_in[15];
    const float* b_hh    = (const float*)d_in[16];
    const float* W_out   = (const float*)d_in[17];
    const float* b_out   = (const float*)d_in[18];
    float* out = (float*)d_out;

    float *px, *pq, *pk, *pV, *psc, *pcat, *pmha, *pxln, *pgi;
    cudaGetSymbolAddress((void**)&px,   g_x);
    cudaGetSymbolAddress((void**)&pq,   g_q);
    cudaGetSymbolAddress((void**)&pk,   g_k);
    cudaGetSymbolAddress((void**)&pV,   g_v);
    cudaGetSymbolAddress((void**)&psc,  g_sc);
    cudaGetSymbolAddress((void**)&pcat, g_cat);
    cudaGetSymbolAddress((void**)&pmha, g_mha);
    cudaGetSymbolAddress((void**)&pxln, g_xln);
    cudaGetSymbolAddress((void**)&pgi,  g_gi);

    // 1) embedding gather
    embed_kernel<<<SEQ, 128>>>(tok, emb);

    // 2) Q/K/V projections: (2048x512)@(512x512) per head, batched over heads
    gemm128<false><<<dim3(4,16,NH), 256>>>(px, Wq, bq, pq, SEQ, HDIM, HDIM,
        HDIM, HDIM, HDIM, 0LL, (long long)HDIM*HDIM, (long long)SEQ*HDIM, HDIM, 1.0f);
    gemm128<false><<<dim3(4,16,NH), 256>>>(px, Wk, bk, pk, SEQ, HDIM, HDIM,
        HDIM, HDIM, HDIM, 0LL, (long long)HDIM*HDIM, (long long)SEQ*HDIM, HDIM, 1.0f);
    gemm128<false><<<dim3(4,16,NH), 256>>>(px, Wv, bv, pV, SEQ, HDIM, HDIM,
        HDIM, HDIM, HDIM, 0LL, (long long)HDIM*HDIM, (long long)SEQ*HDIM, HDIM, 1.0f);

    // 3) scores = Q @ K^T / sqrt(H)
    gemm128<true><<<dim3(16,16,NH), 256>>>(pq, pk, (const float*)0, psc,
        SEQ, SEQ, HDIM, HDIM, HDIM, SEQ,
        (long long)SEQ*HDIM, (long long)SEQ*HDIM, (long long)SEQ*SEQ, 0LL,
        0.04419417382415922f);

    // 4) softmax over last dim
    softmax2048<<<NH*SEQ, 256>>>(psc);

    // 5) heads = P @ V, written directly into concat layout (col offset h*512)
    gemm128<false><<<dim3(4,16,NH), 256>>>(psc, pV, (const float*)0, pcat,
        SEQ, HDIM, SEQ, SEQ, HDIM, NH*HDIM,
        (long long)SEQ*SEQ, (long long)SEQ*HDIM, (long long)HDIM, 0LL, 1.0f);

    // 6) mha = cat @ Wo + bo
    gemm128<false><<<dim3(4,16,1), 256>>>(pcat, Wo, bo, pmha,
        SEQ, HDIM, NH*HDIM, NH*HDIM, HDIM, HDIM, 0LL, 0LL, 0LL, 0LL, 1.0f);

    // 7) residual + layernorm
    resid_ln<<<SEQ, 256>>>(gamma, beta);

    // 8) gi = xln @ W_ih^T + b_ih (all timesteps, parallel)
    gemm128<true><<<dim3(12,16,1), 256>>>(pxln, W_ih, b_ih, pgi,
        SEQ, G3, HDIM, HDIM, HDIM, G3, 0LL, 0LL, 0LL, 0LL, 1.0f);

    // 9) sequential GRU (persistent, register-resident W_hh, global barrier)
    gru_init<<<1, 512>>>(dec_hid);
    gru_kernel<<<GRU_NCTA, 256>>>(W_hh, b_hh);

    // 10) logits + log_softmax + outputs
    logits_kernel<<<(VOCAB+255)/256, 256>>>(W_out, b_out);
    lse_kernel<<<1, 1024>>>();
    out_kernel<<<(VOCAB+HDIM+255)/256, 256>>>(out);
}

// round 4
// speedup vs baseline: 1.5860x; 1.5860x over previous
#include <cuda_runtime.h>
#include <cuda_bf16.h>
#include <math.h>

#define SEQ   2048
#define HDIM  512
#define NH    6
#define VOCAB 32000
#define G3    1536          // 3*HDIM
#define GRU_NCTA 64

// ---------------- scratch (device globals; no allocations allowed) -------------
__device__ float g_x   [SEQ*HDIM];                 // embeddings
__device__ float g_q   [NH*SEQ*HDIM];
__device__ float g_k   [NH*SEQ*HDIM];
__device__ float g_v   [NH*SEQ*HDIM];
__device__ float g_sc  [(size_t)NH*SEQ*SEQ];       // attention scores / probs
__device__ float g_cat [SEQ*NH*HDIM];              // concatenated heads (s, h*512+e)
__device__ float g_mha [SEQ*HDIM];
__device__ float g_xln [SEQ*HDIM];                 // post-LN sequence (GRU input)
__device__ float g_gi  [SEQ*G3];                   // x @ W_ih^T + b_ih, all timesteps
__device__ unsigned long long g_ht[2][HDIM];       // tagged hidden: (tag<<32)|f32bits
__device__ float g_logits[VOCAB];
__device__ float g_lse;

__device__ __forceinline__ float sigmoidf_(float x){ return 1.0f/(1.0f+expf(-x)); }

// STRONG (morally strong -> single-copy atomic per PTX model) 64-bit ops.
// Weak .cv/.cg have no formal atomicity guarantee and can tear tag/value —
// that was the R2/R3 corruption source.
__device__ __forceinline__ unsigned long long ld_acq_u64(const unsigned long long* p){
    unsigned long long v;
    asm volatile("ld.acquire.gpu.global.u64 %0, [%1];" : "=l"(v) : "l"(p) : "memory");
    return v;
}
__device__ __forceinline__ void st_rel_u64(unsigned long long* p, unsigned long long v){
    asm volatile("st.release.gpu.global.u64 [%0], %1;" :: "l"(p), "l"(v) : "memory");
}

// ---------------- embedding gather ---------------------------------------------
__global__ void embed_kernel(const int* __restrict__ tok,
                             const float* __restrict__ emb)
{
    int s = blockIdx.x;
    long long t = tok[s];
    const float4* src = (const float4*)(emb + t*HDIM);
    float4* dst = (float4*)(g_x + (long long)s*HDIM);
    int i = threadIdx.x;               // 128 threads, 128 float4 = 512 floats
    dst[i] = src[i];
}

// ---------------- fp32 tiled GEMM: C = alpha*(A@B[^T]) + bias[col] -------------
// BM=BN=128, BK=16, 256 threads, 8x8 microtile per thread.
template<bool TRANS_B>
__global__ void gemm128(const float* __restrict__ A, const float* __restrict__ B,
                        const float* __restrict__ bias, float* __restrict__ C,
                        int M, int N, int K, int lda, int ldb, int ldc,
                        long long sA, long long sB, long long sC, long long sBias,
                        float alpha)
{
    __shared__ float As[16][132];
    __shared__ float Bs[16][132];
    A += (long long)blockIdx.z * sA;
    B += (long long)blockIdx.z * sB;
    C += (long long)blockIdx.z * sC;
    const float* bi = bias ? (bias + (long long)blockIdx.z * sBias) : (const float*)0;

    const int bm = blockIdx.y * 128;
    const int bn = blockIdx.x * 128;
    const int tid = threadIdx.x;
    const int tx = tid & 15, ty = tid >> 4;

    float acc[8][8];
    #pragma unroll
    for (int i = 0; i < 8; i++)
        #pragma unroll
        for (int j = 0; j < 8; j++) acc[i][j] = 0.0f;

    for (int k0 = 0; k0 < K; k0 += 16) {
        #pragma unroll
        for (int i = 0; i < 8; i++) {
            int idx = tid + i*256;
            int m = idx >> 4, k = idx & 15;
            As[k][m] = A[(long long)(bm+m)*lda + (k0+k)];
        }
        #pragma unroll
        for (int i = 0; i < 8; i++) {
            int idx = tid + i*256;
            if (TRANS_B) {
                int n = idx >> 4, k = idx & 15;
                Bs[k][n] = B[(long long)(bn+n)*ldb + (k0+k)];
            } else {
                int k = idx >> 7, n = idx & 127;
                Bs[k][n] = B[(long long)(k0+k)*ldb + (bn+n)];
            }
        }
        __syncthreads();
        #pragma unroll
        for (int kk = 0; kk < 16; kk++) {
            float4 a0 = *(const float4*)&As[kk][ty*8];
            float4 a1 = *(const float4*)&As[kk][ty*8+4];
            float4 b0 = *(const float4*)&Bs[kk][tx*8];
            float4 b1 = *(const float4*)&Bs[kk][tx*8+4];
            float af[8] = {a0.x,a0.y,a0.z,a0.w,a1.x,a1.y,a1.z,a1.w};
            float bf[8] = {b0.x,b0.y,b0.z,b0.w,b1.x,b1.y,b1.z,b1.w};
            #pragma unroll
            for (int i = 0; i < 8; i++)
                #pragma unroll
                for (int j = 0; j < 8; j++)
                    acc[i][j] += af[i]*bf[j];
        }
        __syncthreads();
    }
    #pragma unroll
    for (int i = 0; i < 8; i++) {
        int row = bm + ty*8 + i;
        float* cp = C + (long long)row*ldc + bn + tx*8;
        #pragma unroll
        for (int j = 0; j < 8; j++) {
            float vv = alpha*acc[i][j];
            if (bi) vv += bi[bn + tx*8 + j];
            cp[j] = vv;
        }
    }
}

// ---------------- row softmax over length-2048 rows ----------------------------
__global__ void softmax2048(float* __restrict__ S)
{
    __shared__ float red[32];
    float* row = S + (long long)blockIdx.x * 2048;
    int tid = threadIdx.x;                         // 256
    float v[8];
    float m = -1e30f;
    #pragma unroll
    for (int i = 0; i < 8; i++) { v[i] = row[tid + i*256]; m = fmaxf(m, v[i]); }
    #pragma unroll
    for (int o = 16; o > 0; o >>= 1) m = fmaxf(m, __shfl_xor_sync(~0u, m, o));
    if ((tid & 31) == 0) red[tid >> 5] = m;
    __syncthreads();
    if (tid == 0) {
        float x = red[0];
        #pragma unroll
        for (int i = 1; i < 8; i++) x = fmaxf(x, red[i]);
        red[0] = x;
    }
    __syncthreads();
    m = red[0];
    __syncthreads();
    float s = 0.0f;
    #pragma unroll
    for (int i = 0; i < 8; i++) { v[i] = expf(v[i] - m); s += v[i]; }
    #pragma unroll
    for (int o = 16; o > 0; o >>= 1) s += __shfl_xor_sync(~0u, s, o);
    if ((tid & 31) == 0) red[tid >> 5] = s;
    __syncthreads();
    if (tid == 0) {
        float x = 0.0f;
        #pragma unroll
        for (int i = 0; i < 8; i++) x += red[i];
        red[0] = x;
    }
    __syncthreads();
    float inv = 1.0f / red[0];
    #pragma unroll
    for (int i = 0; i < 8; i++) row[tid + i*256] = v[i]*inv;
}

// ---------------- residual + LayerNorm -----------------------------------------
__global__ void resid_ln(const float* __restrict__ gamma, const float* __restrict__ beta)
{
    __shared__ float r1[8], r2[8];
    int s = blockIdx.x, tid = threadIdx.x;         // 256 threads
    const float* xr = g_x   + (long long)s*HDIM;
    const float* mr = g_mha + (long long)s*HDIM;
    float y0 = xr[tid]       + mr[tid];
    float y1 = xr[tid + 256] + mr[tid + 256];
    float sum = y0 + y1, sq = y0*y0 + y1*y1;
    #pragma unroll
    for (int o = 16; o > 0; o >>= 1) {
        sum += __shfl_xor_sync(~0u, sum, o);
        sq  += __shfl_xor_sync(~0u, sq,  o);
    }
    if ((tid & 31) == 0) { r1[tid >> 5] = sum; r2[tid >> 5] = sq; }
    __syncthreads();
    if (tid == 0) {
        float a = 0.0f, b = 0.0f;
        #pragma unroll
        for (int i = 0; i < 8; i++) { a += r1[i]; b += r2[i]; }
        r1[0] = a; r2[0] = b;
    }
    __syncthreads();
    float mu  = r1[0]*(1.0f/512.0f);
    float var = r2[0]*(1.0f/512.0f) - mu*mu;
    float rstd = rsqrtf(var + 1e-5f);
    g_xln[(long long)s*HDIM + tid]       = (y0 - mu)*rstd*gamma[tid]       + beta[tid];
    g_xln[(long long)s*HDIM + 256 + tid] = (y1 - mu)*rstd*gamma[tid + 256] + beta[tid + 256];
}

// ---------------- GRU init: seed h with tag=1, clear stale tags (graph replay!) -
__global__ void gru_init(const float* __restrict__ dec_hid)
{
    int i = threadIdx.x;                           // 512
    g_ht[0][i] = (1ULL << 32) | (unsigned long long)__float_as_uint(dec_hid[i]);
    g_ht[1][i] = 0ULL;                             // stale-tag clear
}

// ---------------- persistent sequential GRU (tag-in-word dataflow sync) --------
// 64 CTAs x 256 threads. Warp w of CTA c owns h-element jj = c*8+w and its three
// gate rows (jj, jj+512, jj+1024). Lane l holds W_hh[row][l+32i], i=0..15 in regs.
// Step t: each CTA polls ALL 512 words of buf[t&1] for tag t+1 via STRONG
// acquire 64-bit loads (single-copy atomic: tag+value cannot tear), stages into
// smem, CTA barrier, compute, publish hnew into buf[(t+1)&1] with tag t+2 via
// STRONG release store, trailing CTA barrier.
//
// Cross-CTA safety: a producer reaches step t+1 only after acquiring tag t+2
// on ALL 512 slots; each such tag was release-published only after its CTA
// completed the full step-t poll of buf[t&1]. Release->acquire gives causal
// ordering, so every step-t read of a slot happens-before its step-(t+1)
// overwrite. No stale tag can falsely match (per-slot tags advance by +2).
// Intra-CTA safety: the trailing __syncthreads orders this step's hs[] reads
// before next step's hs[] overwrites.
__global__ void gru_kernel(const float* __restrict__ W_hh,
                           const float* __restrict__ b_hh)
{
    __shared__ float hs[HDIM];
    const int tid = threadIdx.x;
    const int warp = tid >> 5, lane = tid & 31;
    const int jj = blockIdx.x * 8 + warp;          // 0..511

    float wr0[16], wr1[16], wr2[16];
    const float* w0 = W_hh + (long long)(jj        )*HDIM + lane;
    const float* w1 = W_hh + (long long)(jj +  512 )*HDIM + lane;
    const float* w2 = W_hh + (long long)(jj + 1024 )*HDIM + lane;
    #pragma unroll
    for (int i = 0; i < 16; i++) { wr0[i] = w0[32*i]; wr1[i] = w1[32*i]; wr2[i] = w2[32*i]; }
    const float bh0 = b_hh[jj], bh1 = b_hh[jj + 512], bh2 = b_hh[jj + 1024];

    for (int t = 0; t < SEQ; t++) {
        // prefetch gi for this step (uniform address across the warp -> broadcast)
        float gr = __ldcg(&g_gi[(long long)t*G3 + jj]);
        float gz = __ldcg(&g_gi[(long long)t*G3 + jj + 512]);
        float gn = __ldcg(&g_gi[(long long)t*G3 + jj + 1024]);

        // poll phase: each thread owns entries tid and tid+256 (CTA covers all 512)
        const unsigned long long* hb = g_ht[t & 1];
        const unsigned expect = (unsigned)(t + 1);
        {
            unsigned long long v0, v1;
            do { v0 = ld_acq_u64(&hb[tid]); }       while ((unsigned)(v0 >> 32) != expect);
            do { v1 = ld_acq_u64(&hb[tid + 256]); } while ((unsigned)(v1 >> 32) != expect);
            hs[tid]       = __uint_as_float((unsigned)v0);
            hs[tid + 256] = __uint_as_float((unsigned)v1);
        }
        __syncthreads();

        float hprev = hs[jj];
        float a0 = 0.0f, a1 = 0.0f, a2 = 0.0f;
        #pragma unroll
        for (int i = 0; i < 16; i++) {
            float h = hs[lane + 32*i];
            a0 += h*wr0[i];
            a1 += h*wr1[i];
            a2 += h*wr2[i];
        }
        #pragma unroll
        for (int o = 16; o > 0; o >>= 1) {
            a0 += __shfl_xor_sync(~0u, a0, o);
            a1 += __shfl_xor_sync(~0u, a1, o);
            a2 += __shfl_xor_sync(~0u, a2, o);
        }

        if (lane == 0) {
            float r = sigmoidf_(gr + a0 + bh0);
            float z = sigmoidf_(gz + a1 + bh1);
            float n = tanhf(gn + r*(a2 + bh2));
            float hnew = (1.0f - z)*n + z*hprev;
            unsigned long long w = ((unsigned long long)(unsigned)(t + 2) << 32)
                                 | (unsigned long long)__float_as_uint(hnew);
            st_rel_u64(&g_ht[(t + 1) & 1][jj], w);
        }
        // order this step's hs[] reads before next step's hs[] writes
        __syncthreads();
    }
}

// ---------------- final projection: logits = h @ W_out + b_out -----------------
// final h (t=2048, tag 2049) lives in g_ht[0] low words
__global__ void logits_kernel(const float* __restrict__ W_out,
                              const float* __restrict__ b_out)
{
    __shared__ float hsm[HDIM];
    for (int i = threadIdx.x; i < HDIM; i += 256)
        hsm[i] = __uint_as_float((unsigned)g_ht[0][i]);
    __syncthreads();
    int v = blockIdx.x*256 + threadIdx.x;
    if (v >= VOCAB) return;
    float acc = b_out[v];
    #pragma unroll 4
    for (int d = 0; d < HDIM; d++) acc += hsm[d]*W_out[(long long)d*VOCAB + v];
    g_logits[v] = acc;
}

__global__ void lse_kernel()
{
    __shared__ float red[32];
    int tid = threadIdx.x;                         // 1024
    float m = -1e30f;
    for (int i = tid; i < VOCAB; i += 1024) m = fmaxf(m, g_logits[i]);
    #pragma unroll
    for (int o = 16; o > 0; o >>= 1) m = fmaxf(m, __shfl_xor_sync(~0u, m, o));
    if ((tid & 31) == 0) red[tid >> 5] = m;
    __syncthreads();
    if (tid == 0) {
        float x = red[0];
        #pragma unroll
        for (int i = 1; i < 32; i++) x = fmaxf(x, red[i]);
        red[0] = x;
    }
    __syncthreads();
    m = red[0];
    __syncthreads();
    float s = 0.0f;
    for (int i = tid; i < VOCAB; i += 1024) s += expf(g_logits[i] - m);
    #pragma unroll
    for (int o = 16; o > 0; o >>= 1) s += __shfl_xor_sync(~0u, s, o);
    if ((tid & 31) == 0) red[tid >> 5] = s;
    __syncthreads();
    if (tid == 0) {
        float x = 0.0f;
        #pragma unroll
        for (int i = 0; i < 32; i++) x += red[i];
        g_lse = m + logf(x);
    }
}

__global__ void out_kernel(float* __restrict__ out)
{
    int i = blockIdx.x*256 + threadIdx.x;
    if (i < VOCAB)            out[i] = g_logits[i] - g_lse;
    else if (i < VOCAB+HDIM)  out[i] = __uint_as_float((unsigned)g_ht[0][i - VOCAB]);
}

// ================================ host side =====================================
extern "C" void kernel_launch(void* const* d_in, const int* in_sizes, int n_in,
                              void* d_out, int out_size)
{
    const int*   tok     = (const int*)  d_in[0];
    const float* dec_hid = (const float*)d_in[1];
    const float* emb     = (const float*)d_in[2];
    const float* Wq      = (const float*)d_in[3];
    const float* bq      = (const float*)d_in[4];
    const float* Wk      = (const float*)d_in[5];
    const float* bk      = (const float*)d_in[6];
    const float* Wv      = (const float*)d_in[7];
    const float* bv      = (const float*)d_in[8];
    const float* Wo      = (const float*)d_in[9];
    const float* bo      = (const float*)d_in[10];
    const float* gamma   = (const float*)d_in[11];
    const float* beta    = (const float*)d_in[12];
    const float* W_ih    = (const float*)d_in[13];
    const float* W_hh    = (const float*)d_in[14];
    const float* b_ih    = (const float*)d_in[15];
    const float* b_hh    = (const float*)d_in[16];
    const float* W_out   = (const float*)d_in[17];
    const float* b_out   = (const float*)d_in[18];
    float* out = (float*)d_out;

    float *px, *pq, *pk, *pV, *psc, *pcat, *pmha, *pxln, *pgi;
    cudaGetSymbolAddress((void**)&px,   g_x);
    cudaGetSymbolAddress((void**)&pq,   g_q);
    cudaGetSymbolAddress((void**)&pk,   g_k);
    cudaGetSymbolAddress((void**)&pV,   g_v);
    cudaGetSymbolAddress((void**)&psc,  g_sc);
    cudaGetSymbolAddress((void**)&pcat, g_cat);
    cudaGetSymbolAddress((void**)&pmha, g_mha);
    cudaGetSymbolAddress((void**)&pxln, g_xln);
    cudaGetSymbolAddress((void**)&pgi,  g_gi);

    // 1) embedding gather
    embed_kernel<<<SEQ, 128>>>(tok, emb);

    // 2) Q/K/V projections: (2048x512)@(512x512) per head, batched over heads
    gemm128<false><<<dim3(4,16,NH), 256>>>(px, Wq, bq, pq, SEQ, HDIM, HDIM,
        HDIM, HDIM, HDIM, 0LL, (long long)HDIM*HDIM, (long long)SEQ*HDIM, HDIM, 1.0f);
    gemm128<false><<<dim3(4,16,NH), 256>>>(px, Wk, bk, pk, SEQ, HDIM, HDIM,
        HDIM, HDIM, HDIM, 0LL, (long long)HDIM*HDIM, (long long)SEQ*HDIM, HDIM, 1.0f);
    gemm128<false><<<dim3(4,16,NH), 256>>>(px, Wv, bv, pV, SEQ, HDIM, HDIM,
        HDIM, HDIM, HDIM, 0LL, (long long)HDIM*HDIM, (long long)SEQ*HDIM, HDIM, 1.0f);

    // 3) scores = Q @ K^T / sqrt(H)
    gemm128<true><<<dim3(16,16,NH), 256>>>(pq, pk, (const float*)0, psc,
        SEQ, SEQ, HDIM, HDIM, HDIM, SEQ,
        (long long)SEQ*HDIM, (long long)SEQ*HDIM, (long long)SEQ*SEQ, 0LL,
        0.04419417382415922f);

    // 4) softmax over last dim
    softmax2048<<<NH*SEQ, 256>>>(psc);

    // 5) heads = P @ V, written directly into concat layout (col offset h*512)
    gemm128<false><<<dim3(4,16,NH), 256>>>(psc, pV, (const float*)0, pcat,
        SEQ, HDIM, SEQ, SEQ, HDIM, NH*HDIM,
        (long long)SEQ*SEQ, (long long)SEQ*HDIM, (long long)HDIM, 0LL, 1.0f);

    // 6) mha = cat @ Wo + bo
    gemm128<false><<<dim3(4,16,1), 256>>>(pcat, Wo, bo, pmha,
        SEQ, HDIM, NH*HDIM, NH*HDIM, HDIM, HDIM, 0LL, 0LL, 0LL, 0LL, 1.0f);

    // 7) residual + layernorm
    resid_ln<<<SEQ, 256>>>(gamma, beta);

    // 8) gi = xln @ W_ih^T + b_ih (all timesteps, parallel)
    gemm128<true><<<dim3(12,16,1), 256>>>(pxln, W_ih, b_ih, pgi,
        SEQ, G3, HDIM, HDIM, HDIM, G3, 0LL, 0LL, 0LL, 0LL, 1.0f);

    // 9) sequential GRU (persistent, register-resident W_hh, tag-word dataflow)
    gru_init<<<1, 512>>>(dec_hid);
    gru_kernel<<<GRU_NCTA, 256>>>(W_hh, b_hh);

    // 10) logits + log_softmax + outputs
    logits_kernel<<<(VOCAB+255)/256, 256>>>(W_out, b_out);
    lse_kernel<<<1, 1024>>>();
    out_kernel<<<(VOCAB+HDIM+255)/256, 256>>>(out);
}

// round 5
// speedup vs baseline: 1.7972x; 1.1332x over previous
#include <cuda_runtime.h>
#include <cuda_bf16.h>
#include <math.h>

#define SEQ   2048
#define HDIM  512
#define NH    6
#define VOCAB 32000
#define G3    1536          // 3*HDIM
#define GRU_NCTA 64

// ---------------- scratch (device globals; no allocations allowed) -------------
__device__ float g_x   [SEQ*HDIM];                 // embeddings
__device__ float g_q   [NH*SEQ*HDIM];
__device__ float g_k   [NH*SEQ*HDIM];
__device__ float g_v   [NH*SEQ*HDIM];
__device__ float g_sc  [(size_t)NH*SEQ*SEQ];       // attention scores / probs
__device__ float g_cat [SEQ*NH*HDIM];              // concatenated heads (s, h*512+e)
__device__ float g_mha [SEQ*HDIM];
__device__ float g_xln [SEQ*HDIM];                 // post-LN sequence (GRU input)
__device__ float g_gi  [SEQ*G3];                   // x @ W_ih^T + b_ih, all timesteps
__device__ unsigned long long g_ht[2][HDIM];       // tagged hidden: (tag<<32)|f32bits
__device__ float g_logits[VOCAB];
__device__ float g_lse;

// STRONG (morally strong -> single-copy atomic per PTX model) 64-bit ops.
__device__ __forceinline__ unsigned long long ld_acq_u64(const unsigned long long* p){
    unsigned long long v;
    asm volatile("ld.acquire.gpu.global.u64 %0, [%1];" : "=l"(v) : "l"(p) : "memory");
    return v;
}
__device__ __forceinline__ void st_rel_u64(unsigned long long* p, unsigned long long v){
    asm volatile("st.release.gpu.global.u64 [%0], %1;" :: "l"(p), "l"(v) : "memory");
}
__device__ __forceinline__ float tanh_fast(float x){
    float y; asm("tanh.approx.f32 %0, %1;" : "=f"(y) : "f"(x)); return y;
}

// ---------------- embedding gather ---------------------------------------------
__global__ void embed_kernel(const int* __restrict__ tok,
                             const float* __restrict__ emb)
{
    int s = blockIdx.x;
    long long t = tok[s];
    const float4* src = (const float4*)(emb + t*HDIM);
    float4* dst = (float4*)(g_x + (long long)s*HDIM);
    int i = threadIdx.x;               // 128 threads, 128 float4 = 512 floats
    dst[i] = src[i];
}

// ---------------- fp32 tiled GEMM: C = alpha*(A@B[^T]) + bias[col] -------------
// BM=BN=128, BK=16, 256 threads, 8x8 microtile, DOUBLE-BUFFERED smem with
// register-staged prefetch of the next k-tile (1 barrier per tile).
template<bool TRANS_B>
__global__ void gemm128(const float* __restrict__ A, const float* __restrict__ B,
                        const float* __restrict__ bias, float* __restrict__ C,
                        int M, int N, int K, int lda, int ldb, int ldc,
                        long long sA, long long sB, long long sC, long long sBias,
                        float alpha)
{
    __shared__ float As[2][16][132];
    __shared__ float Bs[2][16][132];
    A += (long long)blockIdx.z * sA;
    B += (long long)blockIdx.z * sB;
    C += (long long)blockIdx.z * sC;
    const float* bi = bias ? (bias + (long long)blockIdx.z * sBias) : (const float*)0;

    const int bm = blockIdx.y * 128;
    const int bn = blockIdx.x * 128;
    const int tid = threadIdx.x;
    const int tx = tid & 15, ty = tid >> 4;

    float acc[8][8];
    #pragma unroll
    for (int i = 0; i < 8; i++)
        #pragma unroll
        for (int j = 0; j < 8; j++) acc[i][j] = 0.0f;

    float ra[8], rb[8];

    // prologue: load tile 0 into regs
    #pragma unroll
    for (int i = 0; i < 8; i++) {
        int idx = tid + i*256;
        int m = idx >> 4, k = idx & 15;
        ra[i] = A[(long long)(bm+m)*lda + k];
        if (TRANS_B) {
            int n = idx >> 4, kk = idx & 15;
            rb[i] = B[(long long)(bn+n)*ldb + kk];
        } else {
            int kk = idx >> 7, n = idx & 127;
            rb[i] = B[(long long)kk*ldb + (bn+n)];
        }
    }
    // store tile 0 to buffer 0
    #pragma unroll
    for (int i = 0; i < 8; i++) {
        int idx = tid + i*256;
        int m = idx >> 4, k = idx & 15;
        As[0][k][m] = ra[i];
        if (TRANS_B) { int n = idx >> 4, kk = idx & 15; Bs[0][kk][n] = rb[i]; }
        else         { int kk = idx >> 7, n = idx & 127; Bs[0][kk][n] = rb[i]; }
    }
    __syncthreads();

    int cur = 0;
    for (int k0 = 0; k0 < K; k0 += 16) {
        const bool has_next = (k0 + 16 < K);
        // prefetch next tile into regs (overlaps with compute below)
        if (has_next) {
            const int kn = k0 + 16;
            #pragma unroll
            for (int i = 0; i < 8; i++) {
                int idx = tid + i*256;
                int m = idx >> 4, k = idx & 15;
                ra[i] = A[(long long)(bm+m)*lda + (kn+k)];
                if (TRANS_B) {
                    int n = idx >> 4, kk = idx & 15;
                    rb[i] = B[(long long)(bn+n)*ldb + (kn+kk)];
                } else {
                    int kk = idx >> 7, n = idx & 127;
                    rb[i] = B[(long long)(kn+kk)*ldb + (bn+n)];
                }
            }
        }
        // compute on current buffer
        #pragma unroll
        for (int kk = 0; kk < 16; kk++) {
            float4 a0 = *(const float4*)&As[cur][kk][ty*8];
            float4 a1 = *(const float4*)&As[cur][kk][ty*8+4];
            float4 b0 = *(const float4*)&Bs[cur][kk][tx*8];
            float4 b1 = *(const float4*)&Bs[cur][kk][tx*8+4];
            float af[8] = {a0.x,a0.y,a0.z,a0.w,a1.x,a1.y,a1.z,a1.w};
            float bf[8] = {b0.x,b0.y,b0.z,b0.w,b1.x,b1.y,b1.z,b1.w};
            #pragma unroll
            for (int i = 0; i < 8; i++)
                #pragma unroll
                for (int j = 0; j < 8; j++)
                    acc[i][j] += af[i]*bf[j];
        }
        if (has_next) {
            const int nxt = cur ^ 1;
            #pragma unroll
            for (int i = 0; i < 8; i++) {
                int idx = tid + i*256;
                int m = idx >> 4, k = idx & 15;
                As[nxt][k][m] = ra[i];
                if (TRANS_B) { int n = idx >> 4, kk2 = idx & 15; Bs[nxt][kk2][n] = rb[i]; }
                else         { int kk2 = idx >> 7, n = idx & 127; Bs[nxt][kk2][n] = rb[i]; }
            }
            __syncthreads();
            cur = nxt;
        }
    }
    #pragma unroll
    for (int i = 0; i < 8; i++) {
        int row = bm + ty*8 + i;
        float* cp = C + (long long)row*ldc + bn + tx*8;
        #pragma unroll
        for (int j = 0; j < 8; j++) {
            float vv = alpha*acc[i][j];
            if (bi) vv += bi[bn + tx*8 + j];
            cp[j] = vv;
        }
    }
}

// ---------------- row softmax over length-2048 rows ----------------------------
__global__ void softmax2048(float* __restrict__ S)
{
    __shared__ float red[32];
    float* row = S + (long long)blockIdx.x * 2048;
    int tid = threadIdx.x;                         // 256
    float v[8];
    float m = -1e30f;
    #pragma unroll
    for (int i = 0; i < 8; i++) { v[i] = row[tid + i*256]; m = fmaxf(m, v[i]); }
    #pragma unroll
    for (int o = 16; o > 0; o >>= 1) m = fmaxf(m, __shfl_xor_sync(~0u, m, o));
    if ((tid & 31) == 0) red[tid >> 5] = m;
    __syncthreads();
    if (tid == 0) {
        float x = red[0];
        #pragma unroll
        for (int i = 1; i < 8; i++) x = fmaxf(x, red[i]);
        red[0] = x;
    }
    __syncthreads();
    m = red[0];
    __syncthreads();
    float s = 0.0f;
    #pragma unroll
    for (int i = 0; i < 8; i++) { v[i] = expf(v[i] - m); s += v[i]; }
    #pragma unroll
    for (int o = 16; o > 0; o >>= 1) s += __shfl_xor_sync(~0u, s, o);
    if ((tid & 31) == 0) red[tid >> 5] = s;
    __syncthreads();
    if (tid == 0) {
        float x = 0.0f;
        #pragma unroll
        for (int i = 0; i < 8; i++) x += red[i];
        red[0] = x;
    }
    __syncthreads();
    float inv = 1.0f / red[0];
    #pragma unroll
    for (int i = 0; i < 8; i++) row[tid + i*256] = v[i]*inv;
}

// ---------------- residual + LayerNorm -----------------------------------------
__global__ void resid_ln(const float* __restrict__ gamma, const float* __restrict__ beta)
{
    __shared__ float r1[8], r2[8];
    int s = blockIdx.x, tid = threadIdx.x;         // 256 threads
    const float* xr = g_x   + (long long)s*HDIM;
    const float* mr = g_mha + (long long)s*HDIM;
    float y0 = xr[tid]       + mr[tid];
    float y1 = xr[tid + 256] + mr[tid + 256];
    float sum = y0 + y1, sq = y0*y0 + y1*y1;
    #pragma unroll
    for (int o = 16; o > 0; o >>= 1) {
        sum += __shfl_xor_sync(~0u, sum, o);
        sq  += __shfl_xor_sync(~0u, sq,  o);
    }
    if ((tid & 31) == 0) { r1[tid >> 5] = sum; r2[tid >> 5] = sq; }
    __syncthreads();
    if (tid == 0) {
        float a = 0.0f, b = 0.0f;
        #pragma unroll
        for (int i = 0; i < 8; i++) { a += r1[i]; b += r2[i]; }
        r1[0] = a; r2[0] = b;
    }
    __syncthreads();
    float mu  = r1[0]*(1.0f/512.0f);
    float var = r2[0]*(1.0f/512.0f) - mu*mu;
    float rstd = rsqrtf(var + 1e-5f);
    g_xln[(long long)s*HDIM + tid]       = (y0 - mu)*rstd*gamma[tid]       + beta[tid];
    g_xln[(long long)s*HDIM + 256 + tid] = (y1 - mu)*rstd*gamma[tid + 256] + beta[tid + 256];
}

// ---------------- GRU init: seed h with tag=1, clear stale tags (graph replay!) -
__global__ void gru_init(const float* __restrict__ dec_hid)
{
    int i = threadIdx.x;                           // 512
    g_ht[0][i] = (1ULL << 32) | (unsigned long long)__float_as_uint(dec_hid[i]);
    g_ht[1][i] = 0ULL;                             // stale-tag clear
}

// ---------------- persistent sequential GRU (tag-in-word dataflow sync) --------
// 64 CTAs x 256 threads. Warp w of CTA c owns h-element jj = c*8+w and its three
// gate rows. Strong acquire/release 64-bit tag|value words (single-copy atomic).
//
// v2 changes vs R4:
//  - both poll loads issued back-to-back before checking (1 L2 RT discovery)
//  - hs double-buffered in smem -> trailing __syncthreads dropped. Safety: the
//    mid barrier keeps warps within one phase; overwrite of hs[b] happens at
//    step t+2 whose poll is gated on tags proving every warp published step
//    t+1; each publish data-depends on that warp's own completed reads.
//  - MUFU.TANH gates (sigmoid(x) = 0.5 + 0.5*tanh(x/2)).
__global__ void gru_kernel(const float* __restrict__ W_hh,
                           const float* __restrict__ b_hh)
{
    __shared__ float hs[2][HDIM];
    const int tid = threadIdx.x;
    const int warp = tid >> 5, lane = tid & 31;
    const int jj = blockIdx.x * 8 + warp;          // 0..511

    float wr0[16], wr1[16], wr2[16];
    const float* w0 = W_hh + (long long)(jj        )*HDIM + lane;
    const float* w1 = W_hh + (long long)(jj +  512 )*HDIM + lane;
    const float* w2 = W_hh + (long long)(jj + 1024 )*HDIM + lane;
    #pragma unroll
    for (int i = 0; i < 16; i++) { wr0[i] = w0[32*i]; wr1[i] = w1[32*i]; wr2[i] = w2[32*i]; }
    const float bh0 = b_hh[jj], bh1 = b_hh[jj + 512], bh2 = b_hh[jj + 1024];

    for (int t = 0; t < SEQ; t++) {
        // prefetch gi for this step (uniform address across the warp -> broadcast)
        float gr = __ldcg(&g_gi[(long long)t*G3 + jj]);
        float gz = __ldcg(&g_gi[(long long)t*G3 + jj + 512]);
        float gn = __ldcg(&g_gi[(long long)t*G3 + jj + 1024]);

        // poll: both loads in flight before first check
        const unsigned long long* hb = g_ht[t & 1];
        const unsigned expect = (unsigned)(t + 1);
        unsigned long long v0 = ld_acq_u64(&hb[tid]);
        unsigned long long v1 = ld_acq_u64(&hb[tid + 256]);
        while ((unsigned)(v0 >> 32) != expect) v0 = ld_acq_u64(&hb[tid]);
        while ((unsigned)(v1 >> 32) != expect) v1 = ld_acq_u64(&hb[tid + 256]);

        float* hcur = hs[t & 1];
        hcur[tid]       = __uint_as_float((unsigned)v0);
        hcur[tid + 256] = __uint_as_float((unsigned)v1);
        __syncthreads();

        float hprev = hcur[jj];
        float a0 = 0.0f, a1 = 0.0f, a2 = 0.0f;
        #pragma unroll
        for (int i = 0; i < 16; i++) {
            float h = hcur[lane + 32*i];
            a0 += h*wr0[i];
            a1 += h*wr1[i];
            a2 += h*wr2[i];
        }
        #pragma unroll
        for (int o = 16; o > 0; o >>= 1) {
            a0 += __shfl_xor_sync(~0u, a0, o);
            a1 += __shfl_xor_sync(~0u, a1, o);
            a2 += __shfl_xor_sync(~0u, a2, o);
        }

        if (lane == 0) {
            float r = 0.5f + 0.5f*tanh_fast(0.5f*(gr + a0 + bh0));
            float z = 0.5f + 0.5f*tanh_fast(0.5f*(gz + a1 + bh1));
            float n = tanh_fast(gn + r*(a2 + bh2));
            float hnew = fmaf(z, hprev - n, n);    // (1-z)*n + z*h
            unsigned long long w = ((unsigned long long)(unsigned)(t + 2) << 32)
                                 | (unsigned long long)__float_as_uint(hnew);
            st_rel_u64(&g_ht[(t + 1) & 1][jj], w);
        }
        // no trailing barrier: hs is double-buffered (see header comment)
    }
}

// ---------------- final projection: logits = h @ W_out + b_out -----------------
// final h (t=2048, tag 2049) lives in g_ht[0] low words
__global__ void logits_kernel(const float* __restrict__ W_out,
                              const float* __restrict__ b_out)
{
    __shared__ float hsm[HDIM];
    for (int i = threadIdx.x; i < HDIM; i += 256)
        hsm[i] = __uint_as_float((unsigned)g_ht[0][i]);
    __syncthreads();
    int v = blockIdx.x*256 + threadIdx.x;
    if (v >= VOCAB) return;
    float acc = b_out[v];
    #pragma unroll 4
    for (int d = 0; d < HDIM; d++) acc += hsm[d]*W_out[(long long)d*VOCAB + v];
    g_logits[v] = acc;
}

__global__ void lse_kernel()
{
    __shared__ float red[32];
    int tid = threadIdx.x;                         // 1024
    float m = -1e30f;
    for (int i = tid; i < VOCAB; i += 1024) m = fmaxf(m, g_logits[i]);
    #pragma unroll
    for (int o = 16; o > 0; o >>= 1) m = fmaxf(m, __shfl_xor_sync(~0u, m, o));
    if ((tid & 31) == 0) red[tid >> 5] = m;
    __syncthreads();
    if (tid == 0) {
        float x = red[0];
        #pragma unroll
        for (int i = 1; i < 32; i++) x = fmaxf(x, red[i]);
        red[0] = x;
    }
    __syncthreads();
    m = red[0];
    __syncthreads();
    float s = 0.0f;
    for (int i = tid; i < VOCAB; i += 1024) s += expf(g_logits[i] - m);
    #pragma unroll
    for (int o = 16; o > 0; o >>= 1) s += __shfl_xor_sync(~0u, s, o);
    if ((tid & 31) == 0) red[tid >> 5] = s;
    __syncthreads();
    if (tid == 0) {
        float x = 0.0f;
        #pragma unroll
        for (int i = 0; i < 32; i++) x += red[i];
        g_lse = m + logf(x);
    }
}

__global__ void out_kernel(float* __restrict__ out)
{
    int i = blockIdx.x*256 + threadIdx.x;
    if (i < VOCAB)            out[i] = g_logits[i] - g_lse;
    else if (i < VOCAB+HDIM)  out[i] = __uint_as_float((unsigned)g_ht[0][i - VOCAB]);
}

// ================================ host side =====================================
extern "C" void kernel_launch(void* const* d_in, const int* in_sizes, int n_in,
                              void* d_out, int out_size)
{
    const int*   tok     = (const int*)  d_in[0];
    const float* dec_hid = (const float*)d_in[1];
    const float* emb     = (const float*)d_in[2];
    const float* Wq      = (const float*)d_in[3];
    const float* bq      = (const float*)d_in[4];
    const float* Wk      = (const float*)d_in[5];
    const float* bk      = (const float*)d_in[6];
    const float* Wv      = (const float*)d_in[7];
    const float* bv      = (const float*)d_in[8];
    const float* Wo      = (const float*)d_in[9];
    const float* bo      = (const float*)d_in[10];
    const float* gamma   = (const float*)d_in[11];
    const float* beta    = (const float*)d_in[12];
    const float* W_ih    = (const float*)d_in[13];
    const float* W_hh    = (const float*)d_in[14];
    const float* b_ih    = (const float*)d_in[15];
    const float* b_hh    = (const float*)d_in[16];
    const float* W_out   = (const float*)d_in[17];
    const float* b_out   = (const float*)d_in[18];
    float* out = (float*)d_out;

    float *px, *pq, *pk, *pV, *psc, *pcat, *pmha, *pxln, *pgi;
    cudaGetSymbolAddress((void**)&px,   g_x);
    cudaGetSymbolAddress((void**)&pq,   g_q);
    cudaGetSymbolAddress((void**)&pk,   g_k);
    cudaGetSymbolAddress((void**)&pV,   g_v);
    cudaGetSymbolAddress((void**)&psc,  g_sc);
    cudaGetSymbolAddress((void**)&pcat, g_cat);
    cudaGetSymbolAddress((void**)&pmha, g_mha);
    cudaGetSymbolAddress((void**)&pxln, g_xln);
    cudaGetSymbolAddress((void**)&pgi,  g_gi);

    // 1) embedding gather
    embed_kernel<<<SEQ, 128>>>(tok, emb);

    // 2) Q/K/V projections: (2048x512)@(512x512) per head, batched over heads
    gemm128<false><<<dim3(4,16,NH), 256>>>(px, Wq, bq, pq, SEQ, HDIM, HDIM,
        HDIM, HDIM, HDIM, 0LL, (long long)HDIM*HDIM, (long long)SEQ*HDIM, HDIM, 1.0f);
    gemm128<false><<<dim3(4,16,NH), 256>>>(px, Wk, bk, pk, SEQ, HDIM, HDIM,
        HDIM, HDIM, HDIM, 0LL, (long long)HDIM*HDIM, (long long)SEQ*HDIM, HDIM, 1.0f);
    gemm128<false><<<dim3(4,16,NH), 256>>>(px, Wv, bv, pV, SEQ, HDIM, HDIM,
        HDIM, HDIM, HDIM, 0LL, (long long)HDIM*HDIM, (long long)SEQ*HDIM, HDIM, 1.0f);

    // 3) scores = Q @ K^T / sqrt(H)
    gemm128<true><<<dim3(16,16,NH), 256>>>(pq, pk, (const float*)0, psc,
        SEQ, SEQ, HDIM, HDIM, HDIM, SEQ,
        (long long)SEQ*HDIM, (long long)SEQ*HDIM, (long long)SEQ*SEQ, 0LL,
        0.04419417382415922f);

    // 4) softmax over last dim
    softmax2048<<<NH*SEQ, 256>>>(psc);

    // 5) heads = P @ V, written directly into concat layout (col offset h*512)
    gemm128<false><<<dim3(4,16,NH), 256>>>(psc, pV, (const float*)0, pcat,
        SEQ, HDIM, SEQ, SEQ, HDIM, NH*HDIM,
        (long long)SEQ*SEQ, (long long)SEQ*HDIM, (long long)HDIM, 0LL, 1.0f);

    // 6) mha = cat @ Wo + bo
    gemm128<false><<<dim3(4,16,1), 256>>>(pcat, Wo, bo, pmha,
        SEQ, HDIM, NH*HDIM, NH*HDIM, HDIM, HDIM, 0LL, 0LL, 0LL, 0LL, 1.0f);

    // 7) residual + layernorm
    resid_ln<<<SEQ, 256>>>(gamma, beta);

    // 8) gi = xln @ W_ih^T + b_ih (all timesteps, parallel)
    gemm128<true><<<dim3(12,16,1), 256>>>(pxln, W_ih, b_ih, pgi,
        SEQ, G3, HDIM, HDIM, HDIM, G3, 0LL, 0LL, 0LL, 0LL, 1.0f);

    // 9) sequential GRU (persistent, register-resident W_hh, tag-word dataflow)
    gru_init<<<1, 512>>>(dec_hid);
    gru_kernel<<<GRU_NCTA, 256>>>(W_hh, b_hh);

    // 10) logits + log_softmax + outputs
    logits_kernel<<<(VOCAB+255)/256, 256>>>(W_out, b_out);
    lse_kernel<<<1, 1024>>>();
    out_kernel<<<(VOCAB+HDIM+255)/256, 256>>>(out);
}

// round 6
// speedup vs baseline: 2.0179x; 1.1228x over previous
#include <cuda_runtime.h>
#include <cuda_bf16.h>
#include <math.h>

#define SEQ   2048
#define HDIM  512
#define NH    6
#define VOCAB 32000
#define G3    1536          // 3*HDIM
#define GRU_NCTA 64

// ---------------- scratch (device globals; no allocations allowed) -------------
__device__ float g_x   [SEQ*HDIM];                 // embeddings
__device__ float g_q   [NH*SEQ*HDIM];
__device__ float g_k   [NH*SEQ*HDIM];
__device__ float g_v   [NH*SEQ*HDIM];
__device__ float g_sc  [(size_t)NH*SEQ*SEQ];       // attention scores / probs
__device__ float g_cat [SEQ*NH*HDIM];              // concatenated heads (s, h*512+e)
__device__ float g_mha [SEQ*HDIM];
__device__ float g_xln [SEQ*HDIM];                 // post-LN sequence (GRU input)
__device__ float g_gi  [SEQ*G3];                   // x @ W_ih^T + b_ih, all timesteps
__device__ unsigned long long g_ht[2][HDIM];       // tagged hidden: (tag<<32)|f32bits
__device__ float g_logits[VOCAB];
__device__ float g_lse;

// STRONG (morally strong -> single-copy atomic per PTX model) 64-bit ops.
__device__ __forceinline__ unsigned long long ld_acq_u64(const unsigned long long* p){
    unsigned long long v;
    asm volatile("ld.acquire.gpu.global.u64 %0, [%1];" : "=l"(v) : "l"(p) : "memory");
    return v;
}
__device__ __forceinline__ void st_rel_u64(unsigned long long* p, unsigned long long v){
    asm volatile("st.release.gpu.global.u64 [%0], %1;" :: "l"(p), "l"(v) : "memory");
}
__device__ __forceinline__ float tanh_fast(float x){
    float y; asm("tanh.approx.f32 %0, %1;" : "=f"(y) : "f"(x)); return y;
}

// ---------------- embedding gather ---------------------------------------------
__global__ void embed_kernel(const int* __restrict__ tok,
                             const float* __restrict__ emb)
{
    int s = blockIdx.x;
    long long t = tok[s];
    const float4* src = (const float4*)(emb + t*HDIM);
    float4* dst = (float4*)(g_x + (long long)s*HDIM);
    int i = threadIdx.x;               // 128 threads, 128 float4 = 512 floats
    dst[i] = src[i];
}

// ---------------- fp32 tiled GEMM: C = alpha*(A@B[^T]) + bias[col] -------------
// BM=128, BN=64, BK=16, 256 threads, 8x4 microtile, double-buffered smem.
// Sized for 2 CTAs/SM (16 warps) — R5's 8x8 variant was occupancy-starved
// at 1 CTA/SM (regs=154), capping issue at 55%.
template<bool TRANS_B>
__global__ void __launch_bounds__(256, 2)
gemm128(const float* __restrict__ A, const float* __restrict__ B,
        const float* __restrict__ bias, float* __restrict__ C,
        int M, int N, int K, int lda, int ldb, int ldc,
        long long sA, long long sB, long long sC, long long sBias,
        float alpha)
{
    __shared__ float As[2][16][132];
    __shared__ float Bs[2][16][68];
    A += (long long)blockIdx.z * sA;
    B += (long long)blockIdx.z * sB;
    C += (long long)blockIdx.z * sC;
    const float* bi = bias ? (bias + (long long)blockIdx.z * sBias) : (const float*)0;

    const int bm = blockIdx.y * 128;
    const int bn = blockIdx.x * 64;
    const int tid = threadIdx.x;
    const int tx = tid & 15, ty = tid >> 4;        // col group (x4), row group (x8)

    float acc[8][4];
    #pragma unroll
    for (int i = 0; i < 8; i++)
        #pragma unroll
        for (int j = 0; j < 4; j++) acc[i][j] = 0.0f;

    float ra[8], rb[4];

    // prologue: tile 0 -> regs -> buffer 0
    #pragma unroll
    for (int i = 0; i < 8; i++) {
        int idx = tid + i*256;
        int m = idx >> 4, k = idx & 15;
        ra[i] = A[(long long)(bm+m)*lda + k];
    }
    #pragma unroll
    for (int i = 0; i < 4; i++) {
        int idx = tid + i*256;
        if (TRANS_B) { int n = idx >> 4, k = idx & 15; rb[i] = B[(long long)(bn+n)*ldb + k]; }
        else         { int k = idx >> 6, n = idx & 63; rb[i] = B[(long long)k*ldb + (bn+n)]; }
    }
    #pragma unroll
    for (int i = 0; i < 8; i++) {
        int idx = tid + i*256;
        int m = idx >> 4, k = idx & 15;
        As[0][k][m] = ra[i];
    }
    #pragma unroll
    for (int i = 0; i < 4; i++) {
        int idx = tid + i*256;
        if (TRANS_B) { int n = idx >> 4, k = idx & 15; Bs[0][k][n] = rb[i]; }
        else         { int k = idx >> 6, n = idx & 63; Bs[0][k][n] = rb[i]; }
    }
    __syncthreads();

    int cur = 0;
    for (int k0 = 0; k0 < K; k0 += 16) {
        const bool has_next = (k0 + 16 < K);
        if (has_next) {
            const int kn = k0 + 16;
            #pragma unroll
            for (int i = 0; i < 8; i++) {
                int idx = tid + i*256;
                int m = idx >> 4, k = idx & 15;
                ra[i] = A[(long long)(bm+m)*lda + (kn+k)];
            }
            #pragma unroll
            for (int i = 0; i < 4; i++) {
                int idx = tid + i*256;
                if (TRANS_B) { int n = idx >> 4, k = idx & 15; rb[i] = B[(long long)(bn+n)*ldb + (kn+k)]; }
                else         { int k = idx >> 6, n = idx & 63; rb[i] = B[(long long)(kn+k)*ldb + (bn+n)]; }
            }
        }
        #pragma unroll
        for (int kk = 0; kk < 16; kk++) {
            float4 a0 = *(const float4*)&As[cur][kk][ty*8];
            float4 a1 = *(const float4*)&As[cur][kk][ty*8+4];
            float4 b0 = *(const float4*)&Bs[cur][kk][tx*4];
            float af[8] = {a0.x,a0.y,a0.z,a0.w,a1.x,a1.y,a1.z,a1.w};
            float bf[4] = {b0.x,b0.y,b0.z,b0.w};
            #pragma unroll
            for (int i = 0; i < 8; i++)
                #pragma unroll
                for (int j = 0; j < 4; j++)
                    acc[i][j] += af[i]*bf[j];
        }
        if (has_next) {
            const int nxt = cur ^ 1;
            #pragma unroll
            for (int i = 0; i < 8; i++) {
                int idx = tid + i*256;
                int m = idx >> 4, k = idx & 15;
                As[nxt][k][m] = ra[i];
            }
            #pragma unroll
            for (int i = 0; i < 4; i++) {
                int idx = tid + i*256;
                if (TRANS_B) { int n = idx >> 4, k = idx & 15; Bs[nxt][k][n] = rb[i]; }
                else         { int k = idx >> 6, n = idx & 63; Bs[nxt][k][n] = rb[i]; }
            }
            __syncthreads();
            cur = nxt;
        }
    }
    #pragma unroll
    for (int i = 0; i < 8; i++) {
        int row = bm + ty*8 + i;
        float* cp = C + (long long)row*ldc + bn + tx*4;
        #pragma unroll
        for (int j = 0; j < 4; j++) {
            float vv = alpha*acc[i][j];
            if (bi) vv += bi[bn + tx*4 + j];
            cp[j] = vv;
        }
    }
}

// ---------------- row softmax over length-2048 rows ----------------------------
__global__ void softmax2048(float* __restrict__ S)
{
    __shared__ float red[32];
    float* row = S + (long long)blockIdx.x * 2048;
    int tid = threadIdx.x;                         // 256
    float v[8];
    float m = -1e30f;
    #pragma unroll
    for (int i = 0; i < 8; i++) { v[i] = row[tid + i*256]; m = fmaxf(m, v[i]); }
    #pragma unroll
    for (int o = 16; o > 0; o >>= 1) m = fmaxf(m, __shfl_xor_sync(~0u, m, o));
    if ((tid & 31) == 0) red[tid >> 5] = m;
    __syncthreads();
    if (tid == 0) {
        float x = red[0];
        #pragma unroll
        for (int i = 1; i < 8; i++) x = fmaxf(x, red[i]);
        red[0] = x;
    }
    __syncthreads();
    m = red[0];
    __syncthreads();
    float s = 0.0f;
    #pragma unroll
    for (int i = 0; i < 8; i++) { v[i] = __expf(v[i] - m); s += v[i]; }
    #pragma unroll
    for (int o = 16; o > 0; o >>= 1) s += __shfl_xor_sync(~0u, s, o);
    if ((tid & 31) == 0) red[tid >> 5] = s;
    __syncthreads();
    if (tid == 0) {
        float x = 0.0f;
        #pragma unroll
        for (int i = 0; i < 8; i++) x += red[i];
        red[0] = x;
    }
    __syncthreads();
    float inv = 1.0f / red[0];
    #pragma unroll
    for (int i = 0; i < 8; i++) row[tid + i*256] = v[i]*inv;
}

// ---------------- residual + LayerNorm -----------------------------------------
__global__ void resid_ln(const float* __restrict__ gamma, const float* __restrict__ beta)
{
    __shared__ float r1[8], r2[8];
    int s = blockIdx.x, tid = threadIdx.x;         // 256 threads
    const float* xr = g_x   + (long long)s*HDIM;
    const float* mr = g_mha + (long long)s*HDIM;
    float y0 = xr[tid]       + mr[tid];
    float y1 = xr[tid + 256] + mr[tid + 256];
    float sum = y0 + y1, sq = y0*y0 + y1*y1;
    #pragma unroll
    for (int o = 16; o > 0; o >>= 1) {
        sum += __shfl_xor_sync(~0u, sum, o);
        sq  += __shfl_xor_sync(~0u, sq,  o);
    }
    if ((tid & 31) == 0) { r1[tid >> 5] = sum; r2[tid >> 5] = sq; }
    __syncthreads();
    if (tid == 0) {
        float a = 0.0f, b = 0.0f;
        #pragma unroll
        for (int i = 0; i < 8; i++) { a += r1[i]; b += r2[i]; }
        r1[0] = a; r2[0] = b;
    }
    __syncthreads();
    float mu  = r1[0]*(1.0f/512.0f);
    float var = r2[0]*(1.0f/512.0f) - mu*mu;
    float rstd = rsqrtf(var + 1e-5f);
    g_xln[(long long)s*HDIM + tid]       = (y0 - mu)*rstd*gamma[tid]       + beta[tid];
    g_xln[(long long)s*HDIM + 256 + tid] = (y1 - mu)*rstd*gamma[tid + 256] + beta[tid + 256];
}

// ---------------- GRU init: seed h with tag=1, clear stale tags (graph replay!) -
__global__ void gru_init(const float* __restrict__ dec_hid)
{
    int i = threadIdx.x;                           // 512
    g_ht[0][i] = (1ULL << 32) | (unsigned long long)__float_as_uint(dec_hid[i]);
    g_ht[1][i] = 0ULL;                             // stale-tag clear
}

// ---------------- persistent sequential GRU (tag-in-word dataflow sync) --------
// 64 CTAs x 256 threads. Warp w of CTA c owns h-element jj = c*8+w and its three
// gate rows. Strong acquire/release 64-bit tag|value words (single-copy atomic).
__global__ void gru_kernel(const float* __restrict__ W_hh,
                           const float* __restrict__ b_hh)
{
    __shared__ float hs[2][HDIM];
    const int tid = threadIdx.x;
    const int warp = tid >> 5, lane = tid & 31;
    const int jj = blockIdx.x * 8 + warp;          // 0..511

    float wr0[16], wr1[16], wr2[16];
    const float* w0 = W_hh + (long long)(jj        )*HDIM + lane;
    const float* w1 = W_hh + (long long)(jj +  512 )*HDIM + lane;
    const float* w2 = W_hh + (long long)(jj + 1024 )*HDIM + lane;
    #pragma unroll
    for (int i = 0; i < 16; i++) { wr0[i] = w0[32*i]; wr1[i] = w1[32*i]; wr2[i] = w2[32*i]; }
    const float bh0 = b_hh[jj], bh1 = b_hh[jj + 512], bh2 = b_hh[jj + 1024];

    for (int t = 0; t < SEQ; t++) {
        // prefetch gi for this step (uniform address across the warp -> broadcast)
        float gr = __ldcg(&g_gi[(long long)t*G3 + jj]);
        float gz = __ldcg(&g_gi[(long long)t*G3 + jj + 512]);
        float gn = __ldcg(&g_gi[(long long)t*G3 + jj + 1024]);

        // poll: both loads in flight before first check
        const unsigned long long* hb = g_ht[t & 1];
        const unsigned expect = (unsigned)(t + 1);
        unsigned long long v0 = ld_acq_u64(&hb[tid]);
        unsigned long long v1 = ld_acq_u64(&hb[tid + 256]);
        while ((unsigned)(v0 >> 32) != expect) v0 = ld_acq_u64(&hb[tid]);
        while ((unsigned)(v1 >> 32) != expect) v1 = ld_acq_u64(&hb[tid + 256]);

        float* hcur = hs[t & 1];
        hcur[tid]       = __uint_as_float((unsigned)v0);
        hcur[tid + 256] = __uint_as_float((unsigned)v1);
        __syncthreads();

        float hprev = hcur[jj];
        float a0 = 0.0f, a1 = 0.0f, a2 = 0.0f;
        #pragma unroll
        for (int i = 0; i < 16; i++) {
            float h = hcur[lane + 32*i];
            a0 += h*wr0[i];
            a1 += h*wr1[i];
            a2 += h*wr2[i];
        }
        #pragma unroll
        for (int o = 16; o > 0; o >>= 1) {
            a0 += __shfl_xor_sync(~0u, a0, o);
            a1 += __shfl_xor_sync(~0u, a1, o);
            a2 += __shfl_xor_sync(~0u, a2, o);
        }

        if (lane == 0) {
            float r = 0.5f + 0.5f*tanh_fast(0.5f*(gr + a0 + bh0));
            float z = 0.5f + 0.5f*tanh_fast(0.5f*(gz + a1 + bh1));
            float n = tanh_fast(gn + r*(a2 + bh2));
            float hnew = fmaf(z, hprev - n, n);    // (1-z)*n + z*h
            unsigned long long w = ((unsigned long long)(unsigned)(t + 2) << 32)
                                 | (unsigned long long)__float_as_uint(hnew);
            st_rel_u64(&g_ht[(t + 1) & 1][jj], w);
        }
        // no trailing barrier: hs is double-buffered; overwrite of hs[b] occurs at
        // step t+2 whose poll is gated on tags that prove every warp published t+1,
        // and each publish data-depends on that warp's completed reads of hs[b].
    }
}

// ---------------- final projection: logits = h @ W_out + b_out -----------------
// final h (t=2048, tag 2049) lives in g_ht[0] low words
__global__ void logits_kernel(const float* __restrict__ W_out,
                              const float* __restrict__ b_out)
{
    __shared__ float hsm[HDIM];
    for (int i = threadIdx.x; i < HDIM; i += 256)
        hsm[i] = __uint_as_float((unsigned)g_ht[0][i]);
    __syncthreads();
    int v = blockIdx.x*256 + threadIdx.x;
    if (v >= VOCAB) return;
    float acc = b_out[v];
    #pragma unroll 4
    for (int d = 0; d < HDIM; d++) acc += hsm[d]*W_out[(long long)d*VOCAB + v];
    g_logits[v] = acc;
}

__global__ void lse_kernel()
{
    __shared__ float red[32];
    int tid = threadIdx.x;                         // 1024
    float m = -1e30f;
    for (int i = tid; i < VOCAB; i += 1024) m = fmaxf(m, g_logits[i]);
    #pragma unroll
    for (int o = 16; o > 0; o >>= 1) m = fmaxf(m, __shfl_xor_sync(~0u, m, o));
    if ((tid & 31) == 0) red[tid >> 5] = m;
    __syncthreads();
    if (tid == 0) {
        float x = red[0];
        #pragma unroll
        for (int i = 1; i < 32; i++) x = fmaxf(x, red[i]);
        red[0] = x;
    }
    __syncthreads();
    m = red[0];
    __syncthreads();
    float s = 0.0f;
    for (int i = tid; i < VOCAB; i += 1024) s += expf(g_logits[i] - m);
    #pragma unroll
    for (int o = 16; o > 0; o >>= 1) s += __shfl_xor_sync(~0u, s, o);
    if ((tid & 31) == 0) red[tid >> 5] = s;
    __syncthreads();
    if (tid == 0) {
        float x = 0.0f;
        #pragma unroll
        for (int i = 0; i < 32; i++) x += red[i];
        g_lse = m + logf(x);
    }
}

__global__ void out_kernel(float* __restrict__ out)
{
    int i = blockIdx.x*256 + threadIdx.x;
    if (i < VOCAB)            out[i] = g_logits[i] - g_lse;
    else if (i < VOCAB+HDIM)  out[i] = __uint_as_float((unsigned)g_ht[0][i - VOCAB]);
}

// ================================ host side =====================================
extern "C" void kernel_launch(void* const* d_in, const int* in_sizes, int n_in,
                              void* d_out, int out_size)
{
    const int*   tok     = (const int*)  d_in[0];
    const float* dec_hid = (const float*)d_in[1];
    const float* emb     = (const float*)d_in[2];
    const float* Wq      = (const float*)d_in[3];
    const float* bq      = (const float*)d_in[4];
    const float* Wk      = (const float*)d_in[5];
    const float* bk      = (const float*)d_in[6];
    const float* Wv      = (const float*)d_in[7];
    const float* bv      = (const float*)d_in[8];
    const float* Wo      = (const float*)d_in[9];
    const float* bo      = (const float*)d_in[10];
    const float* gamma   = (const float*)d_in[11];
    const float* beta    = (const float*)d_in[12];
    const float* W_ih    = (const float*)d_in[13];
    const float* W_hh    = (const float*)d_in[14];
    const float* b_ih    = (const float*)d_in[15];
    const float* b_hh    = (const float*)d_in[16];
    const float* W_out   = (const float*)d_in[17];
    const float* b_out   = (const float*)d_in[18];
    float* out = (float*)d_out;

    float *px, *pq, *pk, *pV, *psc, *pcat, *pmha, *pxln, *pgi;
    cudaGetSymbolAddress((void**)&px,   g_x);
    cudaGetSymbolAddress((void**)&pq,   g_q);
    cudaGetSymbolAddress((void**)&pk,   g_k);
    cudaGetSymbolAddress((void**)&pV,   g_v);
    cudaGetSymbolAddress((void**)&psc,  g_sc);
    cudaGetSymbolAddress((void**)&pcat, g_cat);
    cudaGetSymbolAddress((void**)&pmha, g_mha);
    cudaGetSymbolAddress((void**)&pxln, g_xln);
    cudaGetSymbolAddress((void**)&pgi,  g_gi);

    // 1) embedding gather
    embed_kernel<<<SEQ, 128>>>(tok, emb);

    // 2) Q/K/V projections: (2048x512)@(512x512) per head, batched over heads
    gemm128<false><<<dim3(8,16,NH), 256>>>(px, Wq, bq, pq, SEQ, HDIM, HDIM,
        HDIM, HDIM, HDIM, 0LL, (long long)HDIM*HDIM, (long long)SEQ*HDIM, HDIM, 1.0f);
    gemm128<false><<<dim3(8,16,NH), 256>>>(px, Wk, bk, pk, SEQ, HDIM, HDIM,
        HDIM, HDIM, HDIM, 0LL, (long long)HDIM*HDIM, (long long)SEQ*HDIM, HDIM, 1.0f);
    gemm128<false><<<dim3(8,16,NH), 256>>>(px, Wv, bv, pV, SEQ, HDIM, HDIM,
        HDIM, HDIM, HDIM, 0LL, (long long)HDIM*HDIM, (long long)SEQ*HDIM, HDIM, 1.0f);

    // 3) scores = Q @ K^T / sqrt(H)
    gemm128<true><<<dim3(32,16,NH), 256>>>(pq, pk, (const float*)0, psc,
        SEQ, SEQ, HDIM, HDIM, HDIM, SEQ,
        (long long)SEQ*HDIM, (long long)SEQ*HDIM, (long long)SEQ*SEQ, 0LL,
        0.04419417382415922f);

    // 4) softmax over last dim
    softmax2048<<<NH*SEQ, 256>>>(psc);

    // 5) heads = P @ V, written directly into concat layout (col offset h*512)
    gemm128<false><<<dim3(8,16,NH), 256>>>(psc, pV, (const float*)0, pcat,
        SEQ, HDIM, SEQ, SEQ, HDIM, NH*HDIM,
        (long long)SEQ*SEQ, (long long)SEQ*HDIM, (long long)HDIM, 0LL, 1.0f);

    // 6) mha = cat @ Wo + bo
    gemm128<false><<<dim3(8,16,1), 256>>>(pcat, Wo, bo, pmha,
        SEQ, HDIM, NH*HDIM, NH*HDIM, HDIM, HDIM, 0LL, 0LL, 0LL, 0LL, 1.0f);

    // 7) residual + layernorm
    resid_ln<<<SEQ, 256>>>(gamma, beta);

    // 8) gi = xln @ W_ih^T + b_ih (all timesteps, parallel)
    gemm128<true><<<dim3(24,16,1), 256>>>(pxln, W_ih, b_ih, pgi,
        SEQ, G3, HDIM, HDIM, HDIM, G3, 0LL, 0LL, 0LL, 0LL, 1.0f);

    // 9) sequential GRU (persistent, register-resident W_hh, tag-word dataflow)
    gru_init<<<1, 512>>>(dec_hid);
    gru_kernel<<<GRU_NCTA, 256>>>(W_hh, b_hh);

    // 10) logits + log_softmax + outputs
    logits_kernel<<<(VOCAB+255)/256, 256>>>(W_out, b_out);
    lse_kernel<<<1, 1024>>>();
    out_kernel<<<(VOCAB+HDIM+255)/256, 256>>>(out);
}